// round 1
// baseline (speedup 1.0000x reference)
#include <cuda_runtime.h>
#include <math.h>

#define D 128
#define D4 32              // D / 4 (float4 lanes per row)
#define MAXN 50000
#define MAXE 800000

// ---------------- scratch (allocation-free: __device__ globals) ----------------
__device__ float g_H [MAXN * D];   // X @ W (shared by both directions)
__device__ float g_A1[MAXN * D];   // agg forward  -> o1/p1 (relu'd in place)
__device__ float g_A2[MAXN * D];   // agg reverse  -> o2/p2
__device__ float g_T [MAXN * D];   // gate pre-activation accumulator
__device__ float g_HM[MAXN * D];   // layer-1 output h
__device__ float g_degF[MAXN];
__device__ float g_degR[MAXN];
__device__ float g_dF[MAXN];       // rsqrt(deg_fwd + 1)
__device__ float g_dR[MAXN];       // rsqrt(deg_rev + 1)
__device__ float g_T11[D * D];     // transposed gate weights (so all GEMMs are A@B)
__device__ float g_T12[D * D];
__device__ float g_T21[D * D];
__device__ float g_T22[D * D];

// ---------------- small elementwise kernels ----------------

__global__ void zero_deg_kernel(float* a, float* b, int n) {
    int i = blockIdx.x * blockDim.x + threadIdx.x;
    if (i < n) { a[i] = 0.f; b[i] = 0.f; }
}

__global__ void deg_kernel(const int* __restrict__ ei, int E, float* dgF, float* dgR) {
    int e = blockIdx.x * blockDim.x + threadIdx.x;
    if (e < E) {
        atomicAdd(dgF + ei[E + e], 1.f);   // dst in-degree (forward)
        atomicAdd(dgR + ei[e],     1.f);   // src out-degree (reverse)
    }
}

__global__ void dinv_kernel(const float* dgF, const float* dgR, float* dF, float* dR, int n) {
    int i = blockIdx.x * blockDim.x + threadIdx.x;
    if (i < n) {
        dF[i] = rsqrtf(dgF[i] + 1.f);
        dR[i] = rsqrtf(dgR[i] + 1.f);
    }
}

__global__ void transpose128(const float* __restrict__ in, float* __restrict__ out) {
    int idx = blockIdx.x * blockDim.x + threadIdx.x;
    if (idx < D * D) {
        int j = idx >> 7, k = idx & 127;
        out[k * D + j] = in[idx];
    }
}

__global__ void zero2_kernel(float* a, float* b, int n4) {
    int i = blockIdx.x * blockDim.x + threadIdx.x;
    if (i < n4) {
        ((float4*)a)[i] = make_float4(0.f, 0.f, 0.f, 0.f);
        ((float4*)b)[i] = make_float4(0.f, 0.f, 0.f, 0.f);
    }
}

// ---------------- GEMM: C[M,128] = A[M,128] @ B[128,128] (+= if accum) ----------------
// Block: 64 rows x 128 cols, 256 threads, 8 warps. ty = warp id (uniform per warp ->
// As reads are broadcast, conflict-free). Each thread: 8 rows x 4 cols (float4 acc).
__global__ void gemm128_kernel(const float* __restrict__ A, const float* __restrict__ B,
                               float* __restrict__ C, int M, int accum) {
    __shared__ float4 Ws[32][32];   // k-chunk x 128 cols (as float4)
    __shared__ float  As[64][32];   // 64 rows x k-chunk
    const int tx = threadIdx.x & 31;
    const int ty = threadIdx.x >> 5;
    const int m0 = blockIdx.x * 64;

    float4 acc[8];
#pragma unroll
    for (int i = 0; i < 8; i++) acc[i] = make_float4(0.f, 0.f, 0.f, 0.f);

    for (int kc = 0; kc < 4; kc++) {
        const int k0 = kc * 32;
        // load B chunk: 32 rows x 32 float4 = 1024 float4, 4 per thread (coalesced)
#pragma unroll
        for (int i = 0; i < 4; i++) {
            int f  = i * 256 + threadIdx.x;
            int kr = f >> 5, j4 = f & 31;
            Ws[kr][j4] = ((const float4*)B)[(k0 + kr) * D4 + j4];
        }
        // load A chunk: 64 rows x 8 float4 = 512 float4, 2 per thread
#pragma unroll
        for (int i = 0; i < 2; i++) {
            int f  = i * 256 + threadIdx.x;
            int r  = f >> 3, c4 = f & 7;
            int gm = m0 + r;
            float4 v = (gm < M) ? ((const float4*)A)[gm * D4 + kc * 8 + c4]
                                : make_float4(0.f, 0.f, 0.f, 0.f);
            *(float4*)&As[r][c4 * 4] = v;
        }
        __syncthreads();
#pragma unroll
        for (int k = 0; k < 32; k++) {
            float4 b = Ws[k][tx];
#pragma unroll
            for (int i = 0; i < 8; i++) {
                float a = As[ty + 8 * i][k];     // warp-uniform -> broadcast
                acc[i].x = fmaf(a, b.x, acc[i].x);
                acc[i].y = fmaf(a, b.y, acc[i].y);
                acc[i].z = fmaf(a, b.z, acc[i].z);
                acc[i].w = fmaf(a, b.w, acc[i].w);
            }
        }
        __syncthreads();
    }
#pragma unroll
    for (int i = 0; i < 8; i++) {
        int gm = m0 + ty + 8 * i;
        if (gm < M) {
            float4* Cp = (float4*)C + gm * D4 + tx;
            if (accum) {
                float4 c = *Cp;
                c.x += acc[i].x; c.y += acc[i].y; c.z += acc[i].z; c.w += acc[i].w;
                *Cp = c;
            } else {
                *Cp = acc[i];
            }
        }
    }
}

// ---------------- edge scatter: one warp per edge, BOTH directions in one pass ----------
// forward: A1[dst] += H[src] * dF[src]*dF[dst]
// reverse: A2[src] += H[dst] * dR[src]*dR[dst]
__global__ void scatter_kernel(const int* __restrict__ ei, int E,
                               const float* __restrict__ H,
                               float* __restrict__ A1, float* __restrict__ A2,
                               const float* __restrict__ dF, const float* __restrict__ dR) {
    int w    = (blockIdx.x * blockDim.x + threadIdx.x) >> 5;
    int lane = threadIdx.x & 31;
    if (w >= E) return;
    int s = ei[w];
    int d = ei[E + w];
    float cf = dF[s] * dF[d];
    float cr = dR[s] * dR[d];
    float4 hs = ((const float4*)H)[s * D4 + lane];
    float4 hd = ((const float4*)H)[d * D4 + lane];
    float4 vf = make_float4(hs.x * cf, hs.y * cf, hs.z * cf, hs.w * cf);
    float4 vr = make_float4(hd.x * cr, hd.y * cr, hd.z * cr, hd.w * cr);
    float* pf = A1 + (size_t)d * D + lane * 4;
    float* pr = A2 + (size_t)s * D + lane * 4;
    asm volatile("red.global.add.v4.f32 [%0], {%1,%2,%3,%4};"
                 :: "l"(pf), "f"(vf.x), "f"(vf.y), "f"(vf.z), "f"(vf.w) : "memory");
    asm volatile("red.global.add.v4.f32 [%0], {%1,%2,%3,%4};"
                 :: "l"(pr), "f"(vr.x), "f"(vr.y), "f"(vr.z), "f"(vr.w) : "memory");
}

// ---------------- self-loop + bias + relu (in place on A1/A2) ----------------
__global__ void selfloop_relu_kernel(const float* __restrict__ H,
                                     float* __restrict__ A1, float* __restrict__ A2,
                                     const float* __restrict__ bc,
                                     const float* __restrict__ dF, const float* __restrict__ dR,
                                     int n4) {
    int idx = blockIdx.x * blockDim.x + threadIdx.x;
    if (idx >= n4) return;
    int n  = idx >> 5;
    int c4 = idx & 31;
    float df = dF[n]; df *= df;
    float dr = dR[n]; dr *= dr;
    float4 h = ((const float4*)H)[idx];
    float4 b = ((const float4*)bc)[c4];
    float4 a1 = ((float4*)A1)[idx];
    a1.x = fmaxf(fmaf(h.x, df, a1.x) + b.x, 0.f);
    a1.y = fmaxf(fmaf(h.y, df, a1.y) + b.y, 0.f);
    a1.z = fmaxf(fmaf(h.z, df, a1.z) + b.z, 0.f);
    a1.w = fmaxf(fmaf(h.w, df, a1.w) + b.w, 0.f);
    ((float4*)A1)[idx] = a1;
    float4 a2 = ((float4*)A2)[idx];
    a2.x = fmaxf(fmaf(h.x, dr, a2.x) + b.x, 0.f);
    a2.y = fmaxf(fmaf(h.y, dr, a2.y) + b.y, 0.f);
    a2.z = fmaxf(fmaf(h.z, dr, a2.z) + b.z, 0.f);
    a2.w = fmaxf(fmaf(h.w, dr, a2.w) + b.w, 0.f);
    ((float4*)A2)[idx] = a2;
}

// ---------------- gate: out = sig(T+b)*o1 + (1-sig)*o2 ----------------
__global__ void gate_kernel(const float* __restrict__ T,
                            const float* __restrict__ O1, const float* __restrict__ O2,
                            const float* __restrict__ bg, float* __restrict__ OUT, int n4) {
    int idx = blockIdx.x * blockDim.x + threadIdx.x;
    if (idx >= n4) return;
    int c4 = idx & 31;
    float4 t  = ((const float4*)T)[idx];
    float4 b  = ((const float4*)bg)[c4];
    float4 o1 = ((const float4*)O1)[idx];
    float4 o2 = ((const float4*)O2)[idx];
    float gx = 1.f / (1.f + __expf(-(t.x + b.x)));
    float gy = 1.f / (1.f + __expf(-(t.y + b.y)));
    float gz = 1.f / (1.f + __expf(-(t.z + b.z)));
    float gw = 1.f / (1.f + __expf(-(t.w + b.w)));
    float4 o;
    o.x = gx * o1.x + (1.f - gx) * o2.x;
    o.y = gy * o1.y + (1.f - gy) * o2.y;
    o.z = gz * o1.z + (1.f - gz) * o2.z;
    o.w = gw * o1.w + (1.f - gw) * o2.w;
    ((float4*)OUT)[idx] = o;
}

// ---------------- driver ----------------
extern "C" void kernel_launch(void* const* d_in, const int* in_sizes, int n_in,
                              void* d_out, int out_size) {
    const float* x   = (const float*)d_in[0];
    const int*   ei  = (const int*)  d_in[1];
    const float* W1  = (const float*)d_in[2];
    const float* bc1 = (const float*)d_in[3];
    const float* W2  = (const float*)d_in[4];
    const float* bc2 = (const float*)d_in[5];
    const float* w11 = (const float*)d_in[6];
    const float* w12 = (const float*)d_in[7];
    const float* b1  = (const float*)d_in[8];
    const float* w21 = (const float*)d_in[9];
    const float* w22 = (const float*)d_in[10];
    const float* b2  = (const float*)d_in[11];

    const int N = in_sizes[0] / D;
    const int E = in_sizes[1] / 2;
    const int n4 = N * D4;

    float *H, *A1, *A2, *T, *HM, *dgF, *dgR, *dF, *dR, *T11, *T12, *T21, *T22;
    cudaGetSymbolAddress((void**)&H,   g_H);
    cudaGetSymbolAddress((void**)&A1,  g_A1);
    cudaGetSymbolAddress((void**)&A2,  g_A2);
    cudaGetSymbolAddress((void**)&T,   g_T);
    cudaGetSymbolAddress((void**)&HM,  g_HM);
    cudaGetSymbolAddress((void**)&dgF, g_degF);
    cudaGetSymbolAddress((void**)&dgR, g_degR);
    cudaGetSymbolAddress((void**)&dF,  g_dF);
    cudaGetSymbolAddress((void**)&dR,  g_dR);
    cudaGetSymbolAddress((void**)&T11, g_T11);
    cudaGetSymbolAddress((void**)&T12, g_T12);
    cudaGetSymbolAddress((void**)&T21, g_T21);
    cudaGetSymbolAddress((void**)&T22, g_T22);

    const int TB = 256;
    const int gN   = (N + TB - 1) / TB;
    const int gE   = (E + TB - 1) / TB;
    const int gND  = (n4 + TB - 1) / TB;
    const int gGemm = (N + 63) / 64;
    const int gScat = (E * 32 + TB - 1) / TB;
    const int gTr  = (D * D + TB - 1) / TB;

    // ---- degrees / normalization (once) ----
    zero_deg_kernel<<<gN, TB>>>(dgF, dgR, N);
    deg_kernel<<<gE, TB>>>(ei, E, dgF, dgR);
    dinv_kernel<<<gN, TB>>>(dgF, dgR, dF, dR, N);

    // ---- transpose gate weights so every GEMM is plain A@B ----
    transpose128<<<gTr, TB>>>(w11, T11);
    transpose128<<<gTr, TB>>>(w12, T12);
    transpose128<<<gTr, TB>>>(w21, T21);
    transpose128<<<gTr, TB>>>(w22, T22);

    // ================= layer 1 =================
    gemm128_kernel<<<gGemm, TB>>>(x, W1, H, N, 0);               // H = x @ W1
    zero2_kernel<<<gND, TB>>>(A1, A2, n4);
    scatter_kernel<<<gScat, TB>>>(ei, E, H, A1, A2, dF, dR);     // both directions
    selfloop_relu_kernel<<<gND, TB>>>(H, A1, A2, bc1, dF, dR, n4); // o1, o2
    gemm128_kernel<<<gGemm, TB>>>(A1, T11, T, N, 0);             // T  = o1 @ w11^T
    gemm128_kernel<<<gGemm, TB>>>(A2, T12, T, N, 1);             // T += o2 @ w12^T
    gate_kernel<<<gND, TB>>>(T, A1, A2, b1, HM, n4);             // h

    // ================= layer 2 =================
    gemm128_kernel<<<gGemm, TB>>>(HM, W2, H, N, 0);              // H = h @ W2
    zero2_kernel<<<gND, TB>>>(A1, A2, n4);
    scatter_kernel<<<gScat, TB>>>(ei, E, H, A1, A2, dF, dR);
    selfloop_relu_kernel<<<gND, TB>>>(H, A1, A2, bc2, dF, dR, n4); // p1, p2
    gemm128_kernel<<<gGemm, TB>>>(A1, T21, T, N, 0);             // T  = p1 @ w21^T
    gemm128_kernel<<<gGemm, TB>>>(A2, T22, T, N, 1);             // T += p2 @ w22^T
    gate_kernel<<<gND, TB>>>(T, A1, A2, b2, (float*)d_out, n4);  // final output
}

// round 2
// speedup vs baseline: 1.2846x; 1.2846x over previous
#include <cuda_runtime.h>
#include <math.h>

#define D 128
#define D4 32
#define MAXN 50000
#define MAXE 800000

// ---------------- scratch ----------------
__device__ float g_H [MAXN * D];
__device__ float g_A1[MAXN * D];
__device__ float g_A2[MAXN * D];
__device__ float g_HM[MAXN * D];
__device__ int   g_degF[MAXN];
__device__ int   g_degR[MAXN];
__device__ int   g_offF[MAXN];
__device__ int   g_offR[MAXN];
__device__ int   g_curF[MAXN];
__device__ int   g_curR[MAXN];
__device__ float g_dF[MAXN];
__device__ float g_dR[MAXN];
__device__ int2  g_csrF[MAXE];     // {src_idx, bitcast(norm_coef)}
__device__ int2  g_csrR[MAXE];     // {dst_idx, bitcast(norm_coef)}
__device__ float g_T11[D * D];
__device__ float g_T12[D * D];
__device__ float g_T21[D * D];
__device__ float g_T22[D * D];

// ---------------- launch 1: zero degree counters ----------------
__global__ void zero_deg_kernel(int* a, int* b, int n) {
    int i = blockIdx.x * blockDim.x + threadIdx.x;
    if (i < n) { a[i] = 0; b[i] = 0; }
}

// ---------------- launch 2: degree histogram ----------------
__global__ void deg_kernel(const int* __restrict__ ei, int E, int* dgF, int* dgR) {
    int e = blockIdx.x * blockDim.x + threadIdx.x;
    if (e < E) {
        atomicAdd(dgF + ei[E + e], 1);   // in-degree (forward dst)
        atomicAdd(dgR + ei[e],     1);   // out-degree (reverse dst = src)
    }
}

// ---------------- launch 3: dinv + all 4 weight transposes ----------------
__global__ void prep_kernel(const int* dgF, const int* dgR, float* dF, float* dR, int n,
                            const float* __restrict__ w11, const float* __restrict__ w12,
                            const float* __restrict__ w21, const float* __restrict__ w22,
                            float* T11, float* T12, float* T21, float* T22) {
    int i = blockIdx.x * blockDim.x + threadIdx.x;
    if (i < n) {
        dF[i] = rsqrtf((float)dgF[i] + 1.f);
        dR[i] = rsqrtf((float)dgR[i] + 1.f);
    }
    if (i < D * D) {
        int j = i >> 7, k = i & 127;
        T11[k * D + j] = w11[i];
        T12[k * D + j] = w12[i];
        T21[k * D + j] = w21[i];
        T22[k * D + j] = w22[i];
    }
}

// ---------------- launch 4: exclusive scan of both degree arrays (single block) -----
__global__ void scan_kernel(const int* degF, const int* degR,
                            int* offF, int* offR, int* curF, int* curR, int n) {
    __shared__ int sF[32], sR[32];
    __shared__ int carryF, carryR;
    int t = threadIdx.x, lane = t & 31, w = t >> 5;
    if (t == 0) { carryF = 0; carryR = 0; }
    __syncthreads();
    for (int base = 0; base < n; base += 1024) {
        int i = base + t;
        int vF = (i < n) ? degF[i] : 0;
        int vR = (i < n) ? degR[i] : 0;
        int iF = vF, iR = vR;
#pragma unroll
        for (int o = 1; o < 32; o <<= 1) {
            int a = __shfl_up_sync(0xffffffffu, iF, o);
            int b = __shfl_up_sync(0xffffffffu, iR, o);
            if (lane >= o) { iF += a; iR += b; }
        }
        if (lane == 31) { sF[w] = iF; sR[w] = iR; }
        __syncthreads();
        if (w == 0) {
            int aF = sF[lane], aR = sR[lane];
#pragma unroll
            for (int o = 1; o < 32; o <<= 1) {
                int a = __shfl_up_sync(0xffffffffu, aF, o);
                int b = __shfl_up_sync(0xffffffffu, aR, o);
                if (lane >= o) { aF += a; aR += b; }
            }
            sF[lane] = aF; sR[lane] = aR;
        }
        __syncthreads();
        int pF = (w > 0) ? sF[w - 1] : 0;
        int pR = (w > 0) ? sR[w - 1] : 0;
        int exF = carryF + pF + iF - vF;
        int exR = carryR + pR + iR - vR;
        if (i < n) { offF[i] = exF; offR[i] = exR; curF[i] = exF; curR[i] = exR; }
        __syncthreads();
        if (t == 0) { carryF += sF[31]; carryR += sR[31]; }
        __syncthreads();
    }
}

// ---------------- launch 5: fill CSR lists with precomputed norm coefs ----------
__global__ void fill_csr_kernel(const int* __restrict__ ei, int E,
                                const float* __restrict__ dF, const float* __restrict__ dR,
                                int* curF, int* curR, int2* csrF, int2* csrR) {
    int e = blockIdx.x * blockDim.x + threadIdx.x;
    if (e >= E) return;
    int s = ei[e];
    int d = ei[E + e];
    float cf = dF[s] * dF[d];
    float cr = dR[s] * dR[d];
    int pF = atomicAdd(curF + d, 1);
    csrF[pF] = make_int2(s, __float_as_int(cf));
    int pR = atomicAdd(curR + s, 1);
    csrR[pR] = make_int2(d, __float_as_int(cr));
}

// ---------------- GEMM: C[M,128] = A[M,128] @ B[128,128] ----------------
__global__ void gemm128_kernel(const float* __restrict__ A, const float* __restrict__ B,
                               float* __restrict__ C, int M) {
    __shared__ float4 Ws[32][32];
    __shared__ float  As[64][32];
    const int tx = threadIdx.x & 31;
    const int ty = threadIdx.x >> 5;
    const int m0 = blockIdx.x * 64;

    float4 acc[8];
#pragma unroll
    for (int i = 0; i < 8; i++) acc[i] = make_float4(0.f, 0.f, 0.f, 0.f);

    for (int kc = 0; kc < 4; kc++) {
        const int k0 = kc * 32;
#pragma unroll
        for (int i = 0; i < 4; i++) {
            int f = i * 256 + threadIdx.x;
            int kr = f >> 5, j4 = f & 31;
            Ws[kr][j4] = ((const float4*)B)[(k0 + kr) * D4 + j4];
        }
#pragma unroll
        for (int i = 0; i < 2; i++) {
            int f = i * 256 + threadIdx.x;
            int r = f >> 3, c4 = f & 7;
            int gm = m0 + r;
            float4 v = (gm < M) ? ((const float4*)A)[gm * D4 + kc * 8 + c4]
                                : make_float4(0.f, 0.f, 0.f, 0.f);
            *(float4*)&As[r][c4 * 4] = v;
        }
        __syncthreads();
#pragma unroll
        for (int k = 0; k < 32; k++) {
            float4 b = Ws[k][tx];
#pragma unroll
            for (int i = 0; i < 8; i++) {
                float a = As[ty + 8 * i][k];
                acc[i].x = fmaf(a, b.x, acc[i].x);
                acc[i].y = fmaf(a, b.y, acc[i].y);
                acc[i].z = fmaf(a, b.z, acc[i].z);
                acc[i].w = fmaf(a, b.w, acc[i].w);
            }
        }
        __syncthreads();
    }
#pragma unroll
    for (int i = 0; i < 8; i++) {
        int gm = m0 + ty + 8 * i;
        if (gm < M) ((float4*)C)[gm * D4 + tx] = acc[i];
    }
}

// ---------------- gather: one warp per node, both directions, fused epilogue ------
// A1[n] = relu( sum_{s in inF(n)} H[s]*coef + H[n]*dF[n]^2 + bias )
// A2[n] = relu( sum_{d in outR(n)} H[d]*coef + H[n]*dR[n]^2 + bias )
__global__ void gather_kernel(const float* __restrict__ H,
                              const int2* __restrict__ csrF, const int2* __restrict__ csrR,
                              const int* __restrict__ offF, const int* __restrict__ offR,
                              const int* __restrict__ degF, const int* __restrict__ degR,
                              const float* __restrict__ dF, const float* __restrict__ dR,
                              const float* __restrict__ bias,
                              float* __restrict__ A1, float* __restrict__ A2, int N) {
    int w = (blockIdx.x * blockDim.x + threadIdx.x) >> 5;
    int lane = threadIdx.x & 31;
    if (w >= N) return;

    float4 acc1 = make_float4(0.f, 0.f, 0.f, 0.f);
    float4 acc2 = make_float4(0.f, 0.f, 0.f, 0.f);

    int oF = offF[w], nF = degF[w];
    for (int b = 0; b < nF; b += 32) {
        int m = min(32, nF - b);
        int2 ent = (lane < m) ? csrF[oF + b + lane] : make_int2(0, 0);
        for (int j = 0; j < m; j++) {
            int   idx = __shfl_sync(0xffffffffu, ent.x, j);
            float c   = __int_as_float(__shfl_sync(0xffffffffu, ent.y, j));
            float4 hv = ((const float4*)H)[idx * D4 + lane];
            acc1.x = fmaf(hv.x, c, acc1.x);
            acc1.y = fmaf(hv.y, c, acc1.y);
            acc1.z = fmaf(hv.z, c, acc1.z);
            acc1.w = fmaf(hv.w, c, acc1.w);
        }
    }
    int oR = offR[w], nR = degR[w];
    for (int b = 0; b < nR; b += 32) {
        int m = min(32, nR - b);
        int2 ent = (lane < m) ? csrR[oR + b + lane] : make_int2(0, 0);
        for (int j = 0; j < m; j++) {
            int   idx = __shfl_sync(0xffffffffu, ent.x, j);
            float c   = __int_as_float(__shfl_sync(0xffffffffu, ent.y, j));
            float4 hv = ((const float4*)H)[idx * D4 + lane];
            acc2.x = fmaf(hv.x, c, acc2.x);
            acc2.y = fmaf(hv.y, c, acc2.y);
            acc2.z = fmaf(hv.z, c, acc2.z);
            acc2.w = fmaf(hv.w, c, acc2.w);
        }
    }
    float4 hn = ((const float4*)H)[w * D4 + lane];
    float4 bb = ((const float4*)bias)[lane];
    float f2 = dF[w]; f2 *= f2;
    float r2 = dR[w]; r2 *= r2;
    float4 a1, a2;
    a1.x = fmaxf(fmaf(hn.x, f2, acc1.x) + bb.x, 0.f);
    a1.y = fmaxf(fmaf(hn.y, f2, acc1.y) + bb.y, 0.f);
    a1.z = fmaxf(fmaf(hn.z, f2, acc1.z) + bb.z, 0.f);
    a1.w = fmaxf(fmaf(hn.w, f2, acc1.w) + bb.w, 0.f);
    a2.x = fmaxf(fmaf(hn.x, r2, acc2.x) + bb.x, 0.f);
    a2.y = fmaxf(fmaf(hn.y, r2, acc2.y) + bb.y, 0.f);
    a2.z = fmaxf(fmaf(hn.z, r2, acc2.z) + bb.z, 0.f);
    a2.w = fmaxf(fmaf(hn.w, r2, acc2.w) + bb.w, 0.f);
    ((float4*)A1)[w * D4 + lane] = a1;
    ((float4*)A2)[w * D4 + lane] = a2;
}

// ---------------- fused gate GEMM: OUT = sig(A1@B1 + A2@B2 + b)*A1 + (1-sig)*A2 ----
__global__ void gate_gemm_kernel(const float* __restrict__ A1, const float* __restrict__ A2,
                                 const float* __restrict__ B1, const float* __restrict__ B2,
                                 const float* __restrict__ bias,
                                 float* __restrict__ OUT, int M) {
    __shared__ float4 Ws[32][32];
    __shared__ float  As[64][32];
    const int tx = threadIdx.x & 31;
    const int ty = threadIdx.x >> 5;
    const int m0 = blockIdx.x * 64;

    float4 acc[8];
#pragma unroll
    for (int i = 0; i < 8; i++) acc[i] = make_float4(0.f, 0.f, 0.f, 0.f);

#pragma unroll
    for (int ph = 0; ph < 2; ph++) {
        const float* A = ph ? A2 : A1;
        const float* B = ph ? B2 : B1;
        for (int kc = 0; kc < 4; kc++) {
            const int k0 = kc * 32;
#pragma unroll
            for (int i = 0; i < 4; i++) {
                int f = i * 256 + threadIdx.x;
                int kr = f >> 5, j4 = f & 31;
                Ws[kr][j4] = ((const float4*)B)[(k0 + kr) * D4 + j4];
            }
#pragma unroll
            for (int i = 0; i < 2; i++) {
                int f = i * 256 + threadIdx.x;
                int r = f >> 3, c4 = f & 7;
                int gm = m0 + r;
                float4 v = (gm < M) ? ((const float4*)A)[gm * D4 + kc * 8 + c4]
                                    : make_float4(0.f, 0.f, 0.f, 0.f);
                *(float4*)&As[r][c4 * 4] = v;
            }
            __syncthreads();
#pragma unroll
            for (int k = 0; k < 32; k++) {
                float4 b = Ws[k][tx];
#pragma unroll
                for (int i = 0; i < 8; i++) {
                    float a = As[ty + 8 * i][k];
                    acc[i].x = fmaf(a, b.x, acc[i].x);
                    acc[i].y = fmaf(a, b.y, acc[i].y);
                    acc[i].z = fmaf(a, b.z, acc[i].z);
                    acc[i].w = fmaf(a, b.w, acc[i].w);
                }
            }
            __syncthreads();
        }
    }
    float4 bb = ((const float4*)bias)[tx];
#pragma unroll
    for (int i = 0; i < 8; i++) {
        int gm = m0 + ty + 8 * i;
        if (gm < M) {
            float4 o1 = ((const float4*)A1)[gm * D4 + tx];
            float4 o2 = ((const float4*)A2)[gm * D4 + tx];
            float gx = 1.f / (1.f + __expf(-(acc[i].x + bb.x)));
            float gy = 1.f / (1.f + __expf(-(acc[i].y + bb.y)));
            float gz = 1.f / (1.f + __expf(-(acc[i].z + bb.z)));
            float gw = 1.f / (1.f + __expf(-(acc[i].w + bb.w)));
            float4 o;
            o.x = gx * o1.x + (1.f - gx) * o2.x;
            o.y = gy * o1.y + (1.f - gy) * o2.y;
            o.z = gz * o1.z + (1.f - gz) * o2.z;
            o.w = gw * o1.w + (1.f - gw) * o2.w;
            ((float4*)OUT)[gm * D4 + tx] = o;
        }
    }
}

// ---------------- driver ----------------
extern "C" void kernel_launch(void* const* d_in, const int* in_sizes, int n_in,
                              void* d_out, int out_size) {
    const float* x   = (const float*)d_in[0];
    const int*   ei  = (const int*)  d_in[1];
    const float* W1  = (const float*)d_in[2];
    const float* bc1 = (const float*)d_in[3];
    const float* W2  = (const float*)d_in[4];
    const float* bc2 = (const float*)d_in[5];
    const float* w11 = (const float*)d_in[6];
    const float* w12 = (const float*)d_in[7];
    const float* b1  = (const float*)d_in[8];
    const float* w21 = (const float*)d_in[9];
    const float* w22 = (const float*)d_in[10];
    const float* b2  = (const float*)d_in[11];

    const int N = in_sizes[0] / D;
    const int E = in_sizes[1] / 2;

    float *H, *A1, *A2, *HM, *dF, *dR, *T11, *T12, *T21, *T22;
    int *degF, *degR, *offF, *offR, *curF, *curR;
    int2 *csrF, *csrR;
    cudaGetSymbolAddress((void**)&H,    g_H);
    cudaGetSymbolAddress((void**)&A1,   g_A1);
    cudaGetSymbolAddress((void**)&A2,   g_A2);
    cudaGetSymbolAddress((void**)&HM,   g_HM);
    cudaGetSymbolAddress((void**)&degF, g_degF);
    cudaGetSymbolAddress((void**)&degR, g_degR);
    cudaGetSymbolAddress((void**)&offF, g_offF);
    cudaGetSymbolAddress((void**)&offR, g_offR);
    cudaGetSymbolAddress((void**)&curF, g_curF);
    cudaGetSymbolAddress((void**)&curR, g_curR);
    cudaGetSymbolAddress((void**)&dF,   g_dF);
    cudaGetSymbolAddress((void**)&dR,   g_dR);
    cudaGetSymbolAddress((void**)&csrF, g_csrF);
    cudaGetSymbolAddress((void**)&csrR, g_csrR);
    cudaGetSymbolAddress((void**)&T11,  g_T11);
    cudaGetSymbolAddress((void**)&T12,  g_T12);
    cudaGetSymbolAddress((void**)&T21,  g_T21);
    cudaGetSymbolAddress((void**)&T22,  g_T22);

    const int TB = 256;
    const int gN    = (N + TB - 1) / TB;
    const int gE    = (E + TB - 1) / TB;
    const int gGemm = (N + 63) / 64;
    const int gGath = (N * 32 + TB - 1) / TB;

    // prelude (5 launches, so launch #6 = gemm128 lands under ncu -s 5 -c 1)
    zero_deg_kernel<<<gN, TB>>>(degF, degR, N);
    deg_kernel<<<gE, TB>>>(ei, E, degF, degR);
    prep_kernel<<<gN, TB>>>(degF, degR, dF, dR, N, w11, w12, w21, w22, T11, T12, T21, T22);
    scan_kernel<<<1, 1024>>>(degF, degR, offF, offR, curF, curR, N);
    fill_csr_kernel<<<gE, TB>>>(ei, E, dF, dR, curF, curR, csrF, csrR);

    // ================= layer 1 =================
    gemm128_kernel<<<gGemm, TB>>>(x, W1, H, N);                              // #6 profiled
    gather_kernel<<<gGath, TB>>>(H, csrF, csrR, offF, offR, degF, degR,
                                 dF, dR, bc1, A1, A2, N);
    gate_gemm_kernel<<<gGemm, TB>>>(A1, A2, T11, T12, b1, HM, N);

    // ================= layer 2 =================
    gemm128_kernel<<<gGemm, TB>>>(HM, W2, H, N);
    gather_kernel<<<gGath, TB>>>(H, csrF, csrR, offF, offR, degF, degR,
                                 dF, dR, bc2, A1, A2, N);
    gate_gemm_kernel<<<gGemm, TB>>>(A1, A2, T21, T22, b2, (float*)d_out, N);
}